// round 10
// baseline (speedup 1.0000x reference)
#include <cuda_runtime.h>

#define C 66            // full tagset incl START/STOP (trans stride)
#define CT 64           // tracked tags (START/STOP provably inert)
#define START_TAG 64
#define STOP_TAG 65
#define NB 32
#define LL 1024
#define DD 1024
#define IMPOSSIBLE_F -10000.0f
#define L2E 1.4426950408889634f
#define LN2F 0.6931471805599453f

// scratch: emissions [B*L, 64] fp32 (8.4 MB)
__device__ float g_feats[(size_t)NB * LL * CT];
// per-(batch, chunk-of-128-steps) readiness flags
__device__ int g_ready[NB * 8];

#define CP_ASYNC16(dst_u32, src_ptr) \
    asm volatile("cp.async.ca.shared.global [%0], [%1], 16;\n" \
                 :: "r"(dst_u32), "l"(src_ptr))
#define CP_COMMIT() asm volatile("cp.async.commit_group;\n" ::: "memory")
#define CP_WAIT6()  asm volatile("cp.async.wait_group 6;\n" ::: "memory")

__global__ void init_kernel()
{
    if (threadIdx.x < NB * 8) g_ready[threadIdx.x] = 0;
}

// ---------------------------------------------------------------------------
// Fused kernel. Blocks 0..255: GEMM producer (chunk-major: batch g&31,
// time-chunk g>>5). Blocks 256..287: CRF forward + gold consumer for one
// batch, gated on per-chunk flags.
// ---------------------------------------------------------------------------
__global__ void __launch_bounds__(256, 2) fused_kernel(
    const float* __restrict__ A, const float* __restrict__ W,
    const float* __restrict__ bias, const float* __restrict__ masks,
    const float* __restrict__ trans, const int* __restrict__ ys32,
    float* __restrict__ out)
{
    __shared__ float Asm[32][128];   // [k][m]              (GEMM)
    __shared__ float Bsm[32][68];    // [k][c], pad 4       (GEMM)
    __shared__ __align__(16) float p_sm[2][CT];             // (forward)
    __shared__ int   k_sm[2];
    __shared__ float msk[LL];
    __shared__ __align__(16) float ring[8][CT];

    const int tid = threadIdx.x;

    if (blockIdx.x < 256) {
        // ================= GEMM producer =================
        const int g = blockIdx.x;
        const int gb = g & 31;        // batch
        const int gc = g >> 5;        // time chunk (0..7)
        const int blockRow = gb * LL + gc * 128;

        const int nt = tid & 7;
        const int mt = tid >> 3;
        const int row_l = tid & 127;
        const int half = tid >> 7;
        const float* aBase = A + (size_t)(blockRow + row_l) * DD + half * 16;

        int kk[8], cc[8];
        #pragma unroll
        for (int s = 0; s < 8; ++s) {
            int idx = tid + 256 * s;
            kk[s] = idx >> 6;
            cc[s] = idx & 63;
        }

        float4 areg[4];
        float breg[8];
        float acc[4][8];
        #pragma unroll
        for (int r = 0; r < 4; ++r)
            #pragma unroll
            for (int j = 0; j < 8; ++j) acc[r][j] = 0.f;

        #pragma unroll
        for (int i = 0; i < 4; ++i) areg[i] = *(const float4*)(aBase + i * 4);
        #pragma unroll
        for (int s = 0; s < 8; ++s) breg[s] = W[kk[s] * C + cc[s]];

        for (int kt = 0; kt < 32; ++kt) {
            __syncthreads();
            #pragma unroll
            for (int i = 0; i < 4; ++i) {
                Asm[half * 16 + i * 4 + 0][row_l] = areg[i].x;
                Asm[half * 16 + i * 4 + 1][row_l] = areg[i].y;
                Asm[half * 16 + i * 4 + 2][row_l] = areg[i].z;
                Asm[half * 16 + i * 4 + 3][row_l] = areg[i].w;
            }
            #pragma unroll
            for (int s = 0; s < 8; ++s) Bsm[kk[s]][cc[s]] = breg[s];
            __syncthreads();

            if (kt + 1 < 32) {
                const float* a2 = aBase + (kt + 1) * 32;
                #pragma unroll
                for (int i = 0; i < 4; ++i) areg[i] = *(const float4*)(a2 + i * 4);
                const float* w2 = W + (size_t)(kt + 1) * 32 * C;
                #pragma unroll
                for (int s = 0; s < 8; ++s) breg[s] = w2[kk[s] * C + cc[s]];
            }

            #pragma unroll 8
            for (int k = 0; k < 32; ++k) {
                float4 av = *(const float4*)&Asm[k][mt * 4];
                float a0 = av.x, a1 = av.y, a2v = av.z, a3 = av.w;
                float4 b0 = *(const float4*)&Bsm[k][nt * 8];
                float4 b1 = *(const float4*)&Bsm[k][nt * 8 + 4];
                float bj[8] = {b0.x, b0.y, b0.z, b0.w, b1.x, b1.y, b1.z, b1.w};
                #pragma unroll
                for (int j = 0; j < 8; ++j) {
                    acc[0][j] = fmaf(a0,  bj[j], acc[0][j]);
                    acc[1][j] = fmaf(a1,  bj[j], acc[1][j]);
                    acc[2][j] = fmaf(a2v, bj[j], acc[2][j]);
                    acc[3][j] = fmaf(a3,  bj[j], acc[3][j]);
                }
            }
        }

        float4 bb0, bb1;
        bb0.x = bias[nt * 8 + 0]; bb0.y = bias[nt * 8 + 1];
        bb0.z = bias[nt * 8 + 2]; bb0.w = bias[nt * 8 + 3];
        bb1.x = bias[nt * 8 + 4]; bb1.y = bias[nt * 8 + 5];
        bb1.z = bias[nt * 8 + 6]; bb1.w = bias[nt * 8 + 7];
        #pragma unroll
        for (int r = 0; r < 4; ++r) {
            size_t row = (size_t)(blockRow + mt * 4 + r);
            float4 o0, o1;
            o0.x = acc[r][0] + bb0.x; o0.y = acc[r][1] + bb0.y;
            o0.z = acc[r][2] + bb0.z; o0.w = acc[r][3] + bb0.w;
            o1.x = acc[r][4] + bb1.x; o1.y = acc[r][5] + bb1.y;
            o1.z = acc[r][6] + bb1.z; o1.w = acc[r][7] + bb1.w;
            *(float4*)&g_feats[row * CT + nt * 8]     = o0;
            *(float4*)&g_feats[row * CT + nt * 8 + 4] = o1;
        }

        __syncthreads();
        __threadfence();
        if (tid == 0) atomicExch(&g_ready[gb * 8 + gc], 1);
        return;
    }

    // ================= forward + gold consumer =================
    const int b = blockIdx.x - 256;
    const int b8 = b * 8;

    // ---------------- gold warp (warp 4) ----------------
    if (tid >= 160) return;
    if (tid >= 128) {
        const int l = tid - 128;
        // ys dtype detect: window in-bounds under both interpretations.
        const int* wnd = ys32 + (size_t)b * LL;
        int v = 0;
        for (int idx = l; idx < 512; idx += 32) v |= wnd[2 * idx + 1];
        #pragma unroll
        for (int o = 16; o; o >>= 1) v |= __shfl_xor_sync(0xffffffffu, v, o);
        const int stride = (v == 0) ? 2 : 1;

        const int* yb = ys32 + (size_t)b * LL * stride;
        const float* mb = masks + (size_t)b * LL;
        float local = 0.f, mloc = 0.f;
        for (int c = 0; c < 8; ++c) {
            if (l == 0)
                while (atomicAdd(&g_ready[b8 + c], 0) == 0) __nanosleep(128);
            __syncwarp();
            for (int t = c * 128 + l; t < (c + 1) * 128; t += 32) {
                int y  = yb[t * stride];
                int yp = t ? yb[(t - 1) * stride] : START_TAG;
                y  = min(max(y,  0), CT - 1);
                yp = min(max(yp, 0), C - 1);
                float mk = mb[t];
                local += (trans[y * C + yp] + g_feats[((size_t)b * LL + t) * CT + y]) * mk;
                mloc  += mk;
            }
        }
        #pragma unroll
        for (int o = 16; o; o >>= 1) {
            local += __shfl_xor_sync(0xffffffffu, local, o);
            mloc  += __shfl_xor_sync(0xffffffffu, mloc,  o);
        }
        if (l == 0) {
            int len = (int)(mloc + 0.5f);
            int last = (len > 0) ? yb[(len - 1) * stride] : START_TAG;
            last = min(max(last, 0), C - 1);
            out[NB + b] = local + trans[STOP_TAG * C + last];
        }
        return;
    }

    // ---------------- recursion warps (0-3) ----------------
    const int i = tid >> 1;     // tag 0..63
    const int q = tid & 1;      // half
    const int j0 = q * 32;

    float E[32];
    #pragma unroll
    for (int jj = 0; jj < 32; ++jj)
        E[jj] = expf(trans[i * C + (j0 + jj)]);

    const float* fb = g_feats + (size_t)b * LL * CT;
    const float* mb = masks + (size_t)b * LL;

    // preload masks (independent of producer)
    for (int idx = tid; idx < LL; idx += 128) msk[idx] = mb[idx];
    if (tid == 0) { k_sm[0] = 0; k_sm[1] = 0; }

    // wait chunk 0, then fold step 0 + ring prologue
    if (tid == 0)
        while (atomicAdd(&g_ready[b8], 0) == 0) __nanosleep(128);
    asm volatile("bar.sync 1, 128;" ::: "memory");
    __threadfence();

    if (q == 0) {
        float mk0 = msk[0];
        float s0 = (mk0 != 0.f) ? (trans[i * C + START_TAG] + fb[i]) : IMPOSSIBLE_F;
        p_sm[0][i] = expf(s0);
    }

    unsigned ring_u32 = (unsigned)__cvta_generic_to_shared(&ring[0][0]);
    if (tid < 16) {
        #pragma unroll
        for (int s = 1; s <= 6; ++s) {
            CP_ASYNC16(ring_u32 + (unsigned)((s & 7) * 256 + tid * 16),
                       fb + (size_t)s * CT + tid * 4);
            CP_COMMIT();
        }
    }

    int ktot = 0;
    int buf = 0;
    for (int t = 1; t < LL; ++t) {
        if (tid < 16) {
            int tp6 = t + 6;
            if (tp6 < LL) {
                if ((tp6 & 127) == 0) {   // entering a new producer chunk
                    int c = tp6 >> 7;
                    while (atomicAdd(&g_ready[b8 + c], 0) == 0) __nanosleep(128);
                }
                CP_ASYNC16(ring_u32 + (unsigned)((tp6 & 7) * 256 + tid * 16),
                           fb + (size_t)tp6 * CT + tid * 4);
            }
            CP_COMMIT();
            CP_WAIT6();          // ring slot for step t complete
        }
        asm volatile("bar.sync 1, 128;" ::: "memory");  // publish p, ring, k

        int k = k_sm[buf];
        ktot += k;
        float scale = __int_as_float((unsigned)(127 - k) << 23);  // exact 2^-k

        float e  = ring[t & 7][i];
        float ee = __expf(e);                 // off critical chain
        float mkt = msk[t];
        float pprev = p_sm[buf][i];

        const float4* pp4 = (const float4*)&p_sm[buf][j0];
        float a0 = 0.f, a1 = 0.f, a2 = 0.f, a3 = 0.f;
        #pragma unroll
        for (int jj = 0; jj < 8; ++jj) {
            float4 pv = pp4[jj];
            a0 = fmaf(E[4 * jj + 0], pv.x, a0);
            a1 = fmaf(E[4 * jj + 1], pv.y, a1);
            a2 = fmaf(E[4 * jj + 2], pv.z, a2);
            a3 = fmaf(E[4 * jj + 3], pv.w, a3);
        }
        float acc = (a0 + a1) + (a2 + a3);
        acc += __shfl_xor_sync(0xffffffffu, acc, 1);

        float w = (mkt != 0.f) ? acc * ee : pprev;
        w *= scale;

        if (q == 0) p_sm[buf ^ 1][i] = w;
        if (tid == 0) {
            unsigned wb = __float_as_uint(w);
            int kn = wb ? (int)((wb >> 23) & 255u) - 127 : 0;
            k_sm[buf ^ 1] = kn;
        }
        buf ^= 1;
    }

    asm volatile("bar.sync 1, 128;" ::: "memory");

    // final: out = lse_i( log(p_i) + K*ln2 + T[STOP,i] ), in log2 space
    if (tid < 32) {
        float Kf = (float)ktot;
        float v0 = __log2f(p_sm[buf][tid])      + Kf + trans[STOP_TAG * C + tid]      * L2E;
        float v1 = __log2f(p_sm[buf][tid + 32]) + Kf + trans[STOP_TAG * C + tid + 32] * L2E;
        float mx = fmaxf(v0, v1);
        #pragma unroll
        for (int o = 16; o; o >>= 1) mx = fmaxf(mx, __shfl_xor_sync(0xffffffffu, mx, o));
        float sum = exp2f(v0 - mx) + exp2f(v1 - mx);
        #pragma unroll
        for (int o = 16; o; o >>= 1) sum += __shfl_xor_sync(0xffffffffu, sum, o);
        if (tid == 0) out[b] = (mx + __log2f(sum)) * LN2F;
    }
}

extern "C" void kernel_launch(void* const* d_in, const int* in_sizes, int n_in,
                              void* d_out, int out_size)
{
    const float* features = (const float*)d_in[0];
    const int*   ys32     = (const int*)d_in[1];
    const float* masks    = (const float*)d_in[2];
    const float* fc_w     = (const float*)d_in[3];
    const float* fc_b     = (const float*)d_in[4];
    const float* trans    = (const float*)d_in[5];
    float* out = (float*)d_out;

    init_kernel<<<1, 256>>>();
    fused_kernel<<<288, 256>>>(features, fc_w, fc_b, masks, trans, ys32, out);
}

// round 12
// speedup vs baseline: 1.4184x; 1.4184x over previous
#include <cuda_runtime.h>
#include <cstdint>

#define C 66            // full tagset incl START/STOP (trans stride)
#define CT 64           // tracked tags (START/STOP provably inert)
#define START_TAG 64
#define STOP_TAG 65
#define NB 32
#define LL 1024
#define DD 1024
#define IMPOSSIBLE_F -10000.0f
#define L2E 1.4426950408889634f
#define LN2F 0.6931471805599453f

// scratch: emissions [B*L, 64] fp32 (8.4 MB)
__device__ float g_feats[(size_t)NB * LL * CT];
// W transposed + bf16 hi/lo split: [64 n][512 k-pairs] u32 (bf16x2, lo=even k)
__device__ unsigned g_wt_h[64 * 512];
__device__ unsigned g_wt_l[64 * 512];

#define CP_ASYNC16(dst_u32, src_ptr) \
    asm volatile("cp.async.ca.shared.global [%0], [%1], 16;\n" \
                 :: "r"(dst_u32), "l"(src_ptr))
#define CP_COMMIT() asm volatile("cp.async.commit_group;\n" ::: "memory")
#define CP_WAIT6()  asm volatile("cp.async.wait_group 6;\n" ::: "memory")

__device__ __forceinline__ void mma16816(float* d, const unsigned* a,
                                         unsigned b0, unsigned b1) {
    asm volatile(
        "mma.sync.aligned.m16n8k16.row.col.f32.bf16.bf16.f32 "
        "{%0,%1,%2,%3}, {%4,%5,%6,%7}, {%8,%9}, {%0,%1,%2,%3};\n"
        : "+f"(d[0]), "+f"(d[1]), "+f"(d[2]), "+f"(d[3])
        : "r"(a[0]), "r"(a[1]), "r"(a[2]), "r"(a[3]), "r"(b0), "r"(b1));
}

// ---------------------------------------------------------------------------
// W prep: Wt[n][kp] = bf16x2{ W[2kp][n], W[2kp+1][n] } hi + residual lo.
// ---------------------------------------------------------------------------
__global__ void wprep_kernel(const float* __restrict__ W)
{
    int P = blockIdx.x * 256 + threadIdx.x;     // 0..32767
    if (P >= 64 * 512) return;
    int n = P >> 9, kp = P & 511;
    float x0 = W[(size_t)(2 * kp) * C + n];
    float x1 = W[(size_t)(2 * kp + 1) * C + n];
    unsigned h;
    asm("cvt.rn.bf16x2.f32 %0, %1, %2;" : "=r"(h) : "f"(x1), "f"(x0));
    float l0 = x0 - __uint_as_float(h << 16);
    float l1 = x1 - __uint_as_float(h & 0xffff0000u);
    unsigned l;
    asm("cvt.rn.bf16x2.f32 %0, %1, %2;" : "=r"(l) : "f"(l1), "f"(l0));
    g_wt_h[P] = h;
    g_wt_l[P] = l;
}

// ---------------------------------------------------------------------------
// HMMA GEMM: feats = A * W + bias via bf16 hi/lo split (3 mma passes, f32 acc).
// CTA 256 thr / 8 warps, tile M=128 x N=64, 16 K-chunks of 64.
// Smem (u32 units, row stride 36 = conflict-free for fragment LDS):
//   Ah[128][36], Al[128][36], Bh[64][36], Bl[64][36], bias[64]
// ---------------------------------------------------------------------------
#define AH_OFF 0
#define AL_OFF 4608
#define BH_OFF 9216
#define BL_OFF 11520
#define BIAS_OFF 13824
#define SMEM_U32 13888

__global__ void __launch_bounds__(256, 2) hmma_kernel(
    const float* __restrict__ A, const float* __restrict__ bias)
{
    extern __shared__ unsigned sm[];
    unsigned* Ah = sm + AH_OFF;
    unsigned* Al = sm + AL_OFF;
    unsigned* Bh = sm + BH_OFF;
    unsigned* Bl = sm + BL_OFF;
    float* bsm = (float*)(sm + BIAS_OFF);

    const int tid = threadIdx.x;
    const int w = tid >> 5;
    const int lane = tid & 31;
    const int g = lane >> 2;        // group (row within fragment)
    const int tig = lane & 3;       // thread in group (k-pair)
    const int blockRow = blockIdx.x * 128;

    if (tid < 64) bsm[tid] = bias[tid];

    // A staging: thread owns row am, k-half ah (32 floats per chunk)
    const int am = tid >> 1;
    const int ah = tid & 1;
    const float4* asrc = (const float4*)(A + (size_t)(blockRow + am) * DD + ah * 32);

    float4 pre[8];
    #pragma unroll
    for (int j = 0; j < 8; ++j) pre[j] = asrc[j];

    float acc[8][4];
    #pragma unroll
    for (int nt = 0; nt < 8; ++nt)
        #pragma unroll
        for (int r = 0; r < 4; ++r) acc[nt][r] = 0.f;

    const int m0 = w * 16;

    for (int chunk = 0; chunk < 16; ++chunk) {
        // ---- convert + STS A (hi/lo split) ----
        const unsigned abase = (unsigned)(am * 36 + ah * 16);
        #pragma unroll
        for (int j = 0; j < 8; ++j) {
            float4 v = pre[j];
            unsigned h0, h1, l0, l1;
            asm("cvt.rn.bf16x2.f32 %0, %1, %2;" : "=r"(h0) : "f"(v.y), "f"(v.x));
            asm("cvt.rn.bf16x2.f32 %0, %1, %2;" : "=r"(h1) : "f"(v.w), "f"(v.z));
            float r0 = v.x - __uint_as_float(h0 << 16);
            float r1 = v.y - __uint_as_float(h0 & 0xffff0000u);
            float r2 = v.z - __uint_as_float(h1 << 16);
            float r3 = v.w - __uint_as_float(h1 & 0xffff0000u);
            asm("cvt.rn.bf16x2.f32 %0, %1, %2;" : "=r"(l0) : "f"(r1), "f"(r0));
            asm("cvt.rn.bf16x2.f32 %0, %1, %2;" : "=r"(l1) : "f"(r3), "f"(r2));
            *(uint2*)&Ah[abase + 2 * j] = make_uint2(h0, h1);
            *(uint2*)&Al[abase + 2 * j] = make_uint2(l0, l1);
        }
        // ---- copy B chunk (pre-split) ----
        {
            const int n = tid >> 2;
            const int kb = (tid & 3) * 8;
            const uint4* gh = (const uint4*)(g_wt_h + n * 512 + chunk * 32 + kb);
            const uint4* gl = (const uint4*)(g_wt_l + n * 512 + chunk * 32 + kb);
            uint4 v0 = gh[0], v1 = gh[1];
            uint4 u0 = gl[0], u1 = gl[1];
            *(uint4*)&Bh[n * 36 + kb]     = v0;
            *(uint4*)&Bh[n * 36 + kb + 4] = v1;
            *(uint4*)&Bl[n * 36 + kb]     = u0;
            *(uint4*)&Bl[n * 36 + kb + 4] = u1;
        }
        __syncthreads();

        if (chunk + 1 < 16) {   // prefetch next A chunk
            const float4* s2 = asrc + (chunk + 1) * 16;
            #pragma unroll
            for (int j = 0; j < 8; ++j) pre[j] = s2[j];
        }

        // ---- compute: 4 k16-steps ----
        #pragma unroll
        for (int ks = 0; ks < 4; ++ks) {
            const unsigned kb = (unsigned)(ks * 8 + tig);
            unsigned ahi[4], alo[4];
            ahi[0] = Ah[(m0 + g) * 36 + kb];
            ahi[1] = Ah[(m0 + g + 8) * 36 + kb];
            ahi[2] = Ah[(m0 + g) * 36 + kb + 4];
            ahi[3] = Ah[(m0 + g + 8) * 36 + kb + 4];
            alo[0] = Al[(m0 + g) * 36 + kb];
            alo[1] = Al[(m0 + g + 8) * 36 + kb];
            alo[2] = Al[(m0 + g) * 36 + kb + 4];
            alo[3] = Al[(m0 + g + 8) * 36 + kb + 4];
            #pragma unroll
            for (int nt = 0; nt < 8; ++nt) {
                const unsigned bidx = (unsigned)((nt * 8 + g) * 36) + kb;
                unsigned bh0 = Bh[bidx], bh1 = Bh[bidx + 4];
                unsigned bl0 = Bl[bidx], bl1 = Bl[bidx + 4];
                mma16816(acc[nt], ahi, bh0, bh1);
                mma16816(acc[nt], ahi, bl0, bl1);
                mma16816(acc[nt], alo, bh0, bh1);
            }
        }
        __syncthreads();
    }

    // ---- epilogue: + bias, store f32 ----
    const int r0 = blockRow + m0 + g;
    #pragma unroll
    for (int nt = 0; nt < 8; ++nt) {
        const int c = nt * 8 + tig * 2;
        float b0 = bsm[c], b1 = bsm[c + 1];
        float2 o0 = make_float2(acc[nt][0] + b0, acc[nt][1] + b1);
        float2 o1 = make_float2(acc[nt][2] + b0, acc[nt][3] + b1);
        *(float2*)&g_feats[(size_t)r0 * CT + c]       = o0;
        *(float2*)&g_feats[(size_t)(r0 + 8) * CT + c] = o1;
    }
}

// ---------------------------------------------------------------------------
// CRF forward in probability space + fused gold score (unchanged, validated).
// ---------------------------------------------------------------------------
__global__ void __launch_bounds__(160, 1) forward_kernel(
    const float* __restrict__ masks, const float* __restrict__ trans,
    const int* __restrict__ ys32, float* __restrict__ out)
{
    const int b = blockIdx.x;
    const int tid = threadIdx.x;

    __shared__ __align__(16) float p_sm[2][CT];
    __shared__ int   k_sm[2];
    __shared__ float msk[LL];
    __shared__ __align__(16) float ring[8][CT];

    // ---------------- gold warp (warp 4) ----------------
    if (tid >= 128) {
        const int l = tid - 128;
        const int* wnd = ys32 + (size_t)b * LL;
        int v = 0;
        for (int idx = l; idx < 512; idx += 32) v |= wnd[2 * idx + 1];
        #pragma unroll
        for (int o = 16; o; o >>= 1) v |= __shfl_xor_sync(0xffffffffu, v, o);
        const int stride = (v == 0) ? 2 : 1;

        const int* yb = ys32 + (size_t)b * LL * stride;
        const float* mb = masks + (size_t)b * LL;
        float local = 0.f, mloc = 0.f;
        for (int t = l; t < LL; t += 32) {
            int y  = yb[t * stride];
            int yp = t ? yb[(t - 1) * stride] : START_TAG;
            y  = min(max(y,  0), CT - 1);
            yp = min(max(yp, 0), C - 1);
            float mk = mb[t];
            local += (trans[y * C + yp] + g_feats[((size_t)b * LL + t) * CT + y]) * mk;
            mloc  += mk;
        }
        #pragma unroll
        for (int o = 16; o; o >>= 1) {
            local += __shfl_xor_sync(0xffffffffu, local, o);
            mloc  += __shfl_xor_sync(0xffffffffu, mloc,  o);
        }
        if (l == 0) {
            int len = (int)(mloc + 0.5f);
            int last = (len > 0) ? yb[(len - 1) * stride] : START_TAG;
            last = min(max(last, 0), C - 1);
            out[NB + b] = local + trans[STOP_TAG * C + last];
        }
        return;
    }

    // ---------------- recursion warps ----------------
    const int i = tid >> 1;
    const int q = tid & 1;
    const int j0 = q * 32;

    float E[32];
    #pragma unroll
    for (int jj = 0; jj < 32; ++jj)
        E[jj] = expf(trans[i * C + (j0 + jj)]);

    const float* fb = g_feats + (size_t)b * LL * CT;
    const float* mb = masks + (size_t)b * LL;

    for (int idx = tid; idx < LL; idx += 128) msk[idx] = mb[idx];

    if (q == 0) {
        float mk0 = mb[0];
        float s0 = (mk0 != 0.f) ? (trans[i * C + START_TAG] + fb[i]) : IMPOSSIBLE_F;
        p_sm[0][i] = expf(s0);
    }
    if (tid == 0) { k_sm[0] = 0; k_sm[1] = 0; }

    unsigned ring_u32 = (unsigned)__cvta_generic_to_shared(&ring[0][0]);
    if (tid < 16) {
        #pragma unroll
        for (int s = 1; s <= 6; ++s) {
            CP_ASYNC16(ring_u32 + (unsigned)((s & 7) * 256 + tid * 16),
                       fb + (size_t)s * CT + tid * 4);
            CP_COMMIT();
        }
    }

    int ktot = 0;
    int buf = 0;
    for (int t = 1; t < LL; ++t) {
        if (tid < 16) {
            if (t + 6 < LL)
                CP_ASYNC16(ring_u32 + (unsigned)(((t + 6) & 7) * 256 + tid * 16),
                           fb + (size_t)(t + 6) * CT + tid * 4);
            CP_COMMIT();
            CP_WAIT6();
        }
        asm volatile("bar.sync 1, 128;" ::: "memory");

        int k = k_sm[buf];
        ktot += k;
        float scale = __int_as_float((unsigned)(127 - k) << 23);

        float e  = ring[t & 7][i];
        float ee = __expf(e);
        float mkt = msk[t];
        float pprev = p_sm[buf][i];

        const float4* pp4 = (const float4*)&p_sm[buf][j0];
        float a0 = 0.f, a1 = 0.f, a2 = 0.f, a3 = 0.f;
        #pragma unroll
        for (int jj = 0; jj < 8; ++jj) {
            float4 pv = pp4[jj];
            a0 = fmaf(E[4 * jj + 0], pv.x, a0);
            a1 = fmaf(E[4 * jj + 1], pv.y, a1);
            a2 = fmaf(E[4 * jj + 2], pv.z, a2);
            a3 = fmaf(E[4 * jj + 3], pv.w, a3);
        }
        float acc = (a0 + a1) + (a2 + a3);
        acc += __shfl_xor_sync(0xffffffffu, acc, 1);

        float w = (mkt != 0.f) ? acc * ee : pprev;
        w *= scale;

        if (q == 0) p_sm[buf ^ 1][i] = w;
        if (tid == 0) {
            unsigned wb = __float_as_uint(w);
            int kn = wb ? (int)((wb >> 23) & 255u) - 127 : 0;
            k_sm[buf ^ 1] = kn;
        }
        buf ^= 1;
    }

    asm volatile("bar.sync 1, 128;" ::: "memory");

    if (tid < 32) {
        float Kf = (float)ktot;
        float v0 = __log2f(p_sm[buf][tid])      + Kf + trans[STOP_TAG * C + tid]      * L2E;
        float v1 = __log2f(p_sm[buf][tid + 32]) + Kf + trans[STOP_TAG * C + tid + 32] * L2E;
        float mx = fmaxf(v0, v1);
        #pragma unroll
        for (int o = 16; o; o >>= 1) mx = fmaxf(mx, __shfl_xor_sync(0xffffffffu, mx, o));
        float sum = exp2f(v0 - mx) + exp2f(v1 - mx);
        #pragma unroll
        for (int o = 16; o; o >>= 1) sum += __shfl_xor_sync(0xffffffffu, sum, o);
        if (tid == 0) out[b] = (mx + __log2f(sum)) * LN2F;
    }
}

extern "C" void kernel_launch(void* const* d_in, const int* in_sizes, int n_in,
                              void* d_out, int out_size)
{
    const float* features = (const float*)d_in[0];
    const int*   ys32     = (const int*)d_in[1];
    const float* masks    = (const float*)d_in[2];
    const float* fc_w     = (const float*)d_in[3];
    const float* fc_b     = (const float*)d_in[4];
    const float* trans    = (const float*)d_in[5];
    float* out = (float*)d_out;

    cudaFuncSetAttribute(hmma_kernel, cudaFuncAttributeMaxDynamicSharedMemorySize,
                         SMEM_U32 * 4);

    wprep_kernel<<<128, 256>>>(fc_w);
    hmma_kernel<<<256, 256, SMEM_U32 * 4>>>(features, fc_b);
    forward_kernel<<<NB, 160>>>(masks, trans, ys32, out);
}

// round 13
// speedup vs baseline: 1.6883x; 1.1903x over previous
#include <cuda_runtime.h>
#include <cstdint>

#define C 66            // full tagset incl START/STOP (trans stride)
#define CT 64           // tracked tags (START/STOP provably inert)
#define START_TAG 64
#define STOP_TAG 65
#define NB 32
#define LL 1024
#define DD 1024
#define IMPOSSIBLE_F -10000.0f
#define L2E 1.4426950408889634f
#define LN2F 0.6931471805599453f

// scratch: emissions [B*L, 64] fp32 (8.4 MB)
__device__ float g_feats[(size_t)NB * LL * CT];
// W transposed + bf16 hi/lo split: [64 n][512 k-pairs] u32 (bf16x2)
__device__ unsigned g_wt_h[64 * 512];
__device__ unsigned g_wt_l[64 * 512];

#define CP_ASYNC16(dst_u32, src_ptr) \
    asm volatile("cp.async.ca.shared.global [%0], [%1], 16;\n" \
                 :: "r"(dst_u32), "l"(src_ptr))
#define CP_COMMIT() asm volatile("cp.async.commit_group;\n" ::: "memory")
#define CP_WAIT6()  asm volatile("cp.async.wait_group 6;\n" ::: "memory")

__device__ __forceinline__ void mma16816(float* d, const unsigned* a,
                                         unsigned b0, unsigned b1) {
    asm volatile(
        "mma.sync.aligned.m16n8k16.row.col.f32.bf16.bf16.f32 "
        "{%0,%1,%2,%3}, {%4,%5,%6,%7}, {%8,%9}, {%0,%1,%2,%3};\n"
        : "+f"(d[0]), "+f"(d[1]), "+f"(d[2]), "+f"(d[3])
        : "r"(a[0]), "r"(a[1]), "r"(a[2]), "r"(a[3]), "r"(b0), "r"(b1));
}

__device__ __forceinline__ unsigned long long fma2(unsigned long long a,
                                                   unsigned long long b,
                                                   unsigned long long c) {
    unsigned long long d;
    asm("fma.rn.f32x2 %0, %1, %2, %3;" : "=l"(d) : "l"(a), "l"(b), "l"(c));
    return d;
}
__device__ __forceinline__ unsigned long long add2(unsigned long long a,
                                                   unsigned long long b) {
    unsigned long long d;
    asm("add.rn.f32x2 %0, %1, %2;" : "=l"(d) : "l"(a), "l"(b));
    return d;
}
__device__ __forceinline__ unsigned long long pack2(float lo, float hi) {
    unsigned long long d;
    asm("mov.b64 %0, {%1, %2};" : "=l"(d) : "f"(lo), "f"(hi));
    return d;
}

// ---------------------------------------------------------------------------
// W prep: Wt[n][kp] = bf16x2{ W[2kp][n], W[2kp+1][n] } hi + residual lo.
// ---------------------------------------------------------------------------
__global__ void wprep_kernel(const float* __restrict__ W)
{
    int P = blockIdx.x * 256 + threadIdx.x;
    if (P >= 64 * 512) return;
    int n = P >> 9, kp = P & 511;
    float x0 = W[(size_t)(2 * kp) * C + n];
    float x1 = W[(size_t)(2 * kp + 1) * C + n];
    unsigned h;
    asm("cvt.rn.bf16x2.f32 %0, %1, %2;" : "=r"(h) : "f"(x1), "f"(x0));
    float l0 = x0 - __uint_as_float(h << 16);
    float l1 = x1 - __uint_as_float(h & 0xffff0000u);
    unsigned l;
    asm("cvt.rn.bf16x2.f32 %0, %1, %2;" : "=r"(l) : "f"(l1), "f"(l0));
    g_wt_h[P] = h;
    g_wt_l[P] = l;
}

// ---------------------------------------------------------------------------
// HMMA GEMM (unchanged from R12, validated): bf16 hi/lo split, 3 mma passes.
// ---------------------------------------------------------------------------
#define AH_OFF 0
#define AL_OFF 4608
#define BH_OFF 9216
#define BL_OFF 11520
#define BIAS_OFF 13824
#define SMEM_U32 13888

__global__ void __launch_bounds__(256, 2) hmma_kernel(
    const float* __restrict__ A, const float* __restrict__ bias)
{
    extern __shared__ unsigned sm[];
    unsigned* Ah = sm + AH_OFF;
    unsigned* Al = sm + AL_OFF;
    unsigned* Bh = sm + BH_OFF;
    unsigned* Bl = sm + BL_OFF;
    float* bsm = (float*)(sm + BIAS_OFF);

    const int tid = threadIdx.x;
    const int w = tid >> 5;
    const int lane = tid & 31;
    const int g = lane >> 2;
    const int tig = lane & 3;
    const int blockRow = blockIdx.x * 128;

    if (tid < 64) bsm[tid] = bias[tid];

    const int am = tid >> 1;
    const int ah = tid & 1;
    const float4* asrc = (const float4*)(A + (size_t)(blockRow + am) * DD + ah * 32);

    float4 pre[8];
    #pragma unroll
    for (int j = 0; j < 8; ++j) pre[j] = asrc[j];

    float acc[8][4];
    #pragma unroll
    for (int nt = 0; nt < 8; ++nt)
        #pragma unroll
        for (int r = 0; r < 4; ++r) acc[nt][r] = 0.f;

    const int m0 = w * 16;

    for (int chunk = 0; chunk < 16; ++chunk) {
        const unsigned abase = (unsigned)(am * 36 + ah * 16);
        #pragma unroll
        for (int j = 0; j < 8; ++j) {
            float4 v = pre[j];
            unsigned h0, h1, l0, l1;
            asm("cvt.rn.bf16x2.f32 %0, %1, %2;" : "=r"(h0) : "f"(v.y), "f"(v.x));
            asm("cvt.rn.bf16x2.f32 %0, %1, %2;" : "=r"(h1) : "f"(v.w), "f"(v.z));
            float r0 = v.x - __uint_as_float(h0 << 16);
            float r1 = v.y - __uint_as_float(h0 & 0xffff0000u);
            float r2 = v.z - __uint_as_float(h1 << 16);
            float r3 = v.w - __uint_as_float(h1 & 0xffff0000u);
            asm("cvt.rn.bf16x2.f32 %0, %1, %2;" : "=r"(l0) : "f"(r1), "f"(r0));
            asm("cvt.rn.bf16x2.f32 %0, %1, %2;" : "=r"(l1) : "f"(r3), "f"(r2));
            *(uint2*)&Ah[abase + 2 * j] = make_uint2(h0, h1);
            *(uint2*)&Al[abase + 2 * j] = make_uint2(l0, l1);
        }
        {
            const int n = tid >> 2;
            const int kb = (tid & 3) * 8;
            const uint4* gh = (const uint4*)(g_wt_h + n * 512 + chunk * 32 + kb);
            const uint4* gl = (const uint4*)(g_wt_l + n * 512 + chunk * 32 + kb);
            uint4 v0 = gh[0], v1 = gh[1];
            uint4 u0 = gl[0], u1 = gl[1];
            *(uint4*)&Bh[n * 36 + kb]     = v0;
            *(uint4*)&Bh[n * 36 + kb + 4] = v1;
            *(uint4*)&Bl[n * 36 + kb]     = u0;
            *(uint4*)&Bl[n * 36 + kb + 4] = u1;
        }
        __syncthreads();

        if (chunk + 1 < 16) {
            const float4* s2 = asrc + (chunk + 1) * 16;
            #pragma unroll
            for (int j = 0; j < 8; ++j) pre[j] = s2[j];
        }

        #pragma unroll
        for (int ks = 0; ks < 4; ++ks) {
            const unsigned kb = (unsigned)(ks * 8 + tig);
            unsigned ahi[4], alo[4];
            ahi[0] = Ah[(m0 + g) * 36 + kb];
            ahi[1] = Ah[(m0 + g + 8) * 36 + kb];
            ahi[2] = Ah[(m0 + g) * 36 + kb + 4];
            ahi[3] = Ah[(m0 + g + 8) * 36 + kb + 4];
            alo[0] = Al[(m0 + g) * 36 + kb];
            alo[1] = Al[(m0 + g + 8) * 36 + kb];
            alo[2] = Al[(m0 + g) * 36 + kb + 4];
            alo[3] = Al[(m0 + g + 8) * 36 + kb + 4];
            #pragma unroll
            for (int nt = 0; nt < 8; ++nt) {
                const unsigned bidx = (unsigned)((nt * 8 + g) * 36) + kb;
                unsigned bh0 = Bh[bidx], bh1 = Bh[bidx + 4];
                unsigned bl0 = Bl[bidx], bl1 = Bl[bidx + 4];
                mma16816(acc[nt], ahi, bh0, bh1);
                mma16816(acc[nt], ahi, bl0, bl1);
                mma16816(acc[nt], alo, bh0, bh1);
            }
        }
        __syncthreads();
    }

    const int r0 = blockRow + m0 + g;
    #pragma unroll
    for (int nt = 0; nt < 8; ++nt) {
        const int c = nt * 8 + tig * 2;
        float b0 = bsm[c], b1 = bsm[c + 1];
        float2 o0 = make_float2(acc[nt][0] + b0, acc[nt][1] + b1);
        float2 o1 = make_float2(acc[nt][2] + b0, acc[nt][3] + b1);
        *(float2*)&g_feats[(size_t)r0 * CT + c]       = o0;
        *(float2*)&g_feats[(size_t)(r0 + 8) * CT + c] = o1;
    }
}

// ---------------------------------------------------------------------------
// CRF forward, p-space, f32x2 packed dot. 192 threads:
//   warps 0-3: recursion (tag i = tid>>1, half q = tid&1, 16 FFMA2 + 1 shfl)
//   warp 4:    cp.async ring producer (joins bar.sync 1,160)
//   warp 5:    gold score (independent)
// ---------------------------------------------------------------------------
__global__ void __launch_bounds__(192, 1) forward_kernel(
    const float* __restrict__ masks, const float* __restrict__ trans,
    const int* __restrict__ ys32, float* __restrict__ out)
{
    const int b = blockIdx.x;
    const int tid = threadIdx.x;

    __shared__ __align__(16) float p_sm[2][CT];
    __shared__ int   k_sm[2];
    __shared__ float msk[LL];
    __shared__ __align__(16) float ring[8][CT];

    const float* fb = g_feats + (size_t)b * LL * CT;

    // ---------------- gold warp (warp 5) ----------------
    if (tid >= 160) {
        const int l = tid - 160;
        const int* wnd = ys32 + (size_t)b * LL;
        int v = 0;
        for (int idx = l; idx < 512; idx += 32) v |= wnd[2 * idx + 1];
        #pragma unroll
        for (int o = 16; o; o >>= 1) v |= __shfl_xor_sync(0xffffffffu, v, o);
        const int stride = (v == 0) ? 2 : 1;

        const int* yb = ys32 + (size_t)b * LL * stride;
        const float* mb = masks + (size_t)b * LL;
        float local = 0.f, mloc = 0.f;
        for (int t = l; t < LL; t += 32) {
            int y  = yb[t * stride];
            int yp = t ? yb[(t - 1) * stride] : START_TAG;
            y  = min(max(y,  0), CT - 1);
            yp = min(max(yp, 0), C - 1);
            float mk = mb[t];
            local += (trans[y * C + yp] + fb[(size_t)t * CT + y]) * mk;
            mloc  += mk;
        }
        #pragma unroll
        for (int o = 16; o; o >>= 1) {
            local += __shfl_xor_sync(0xffffffffu, local, o);
            mloc  += __shfl_xor_sync(0xffffffffu, mloc,  o);
        }
        if (l == 0) {
            int len = (int)(mloc + 0.5f);
            int last = (len > 0) ? yb[(len - 1) * stride] : START_TAG;
            last = min(max(last, 0), C - 1);
            out[NB + b] = local + trans[STOP_TAG * C + last];
        }
        return;
    }

    // ---------------- ring producer warp (warp 4) ----------------
    if (tid >= 128) {
        const int l = tid - 128;
        unsigned ring_u32 = (unsigned)__cvta_generic_to_shared(&ring[0][0]);
        if (l < 16) {
            #pragma unroll
            for (int s = 1; s <= 6; ++s) {
                CP_ASYNC16(ring_u32 + (unsigned)((s & 7) * 256 + l * 16),
                           fb + (size_t)s * CT + l * 4);
                CP_COMMIT();
            }
        }
        for (int t = 1; t < LL; ++t) {
            if (l < 16) {
                int tp6 = t + 6;
                if (tp6 < LL)
                    CP_ASYNC16(ring_u32 + (unsigned)((tp6 & 7) * 256 + l * 16),
                               fb + (size_t)tp6 * CT + l * 4);
                CP_COMMIT();
                CP_WAIT6();
            }
            asm volatile("bar.sync 1, 160;" ::: "memory");
        }
        asm volatile("bar.sync 1, 160;" ::: "memory");   // final
        return;
    }

    // ---------------- recursion warps (0-3) ----------------
    const int i = tid >> 1;
    const int q = tid & 1;
    const int j0 = q * 32;

    unsigned long long E[16];     // packed f32x2 exp(T) row-half
    #pragma unroll
    for (int jj = 0; jj < 16; ++jj) {
        float e0 = expf(trans[i * C + (j0 + 2 * jj)]);
        float e1 = expf(trans[i * C + (j0 + 2 * jj + 1)]);
        E[jj] = pack2(e0, e1);
    }

    const float* mb = masks + (size_t)b * LL;
    for (int idx = tid; idx < LL; idx += 128) msk[idx] = mb[idx];

    if (q == 0) {
        float mk0 = mb[0];
        float s0 = (mk0 != 0.f) ? (trans[i * C + START_TAG] + fb[i]) : IMPOSSIBLE_F;
        p_sm[0][i] = expf(s0);
    }
    if (tid == 0) { k_sm[0] = 0; k_sm[1] = 0; }

    int ktot = 0;
    int buf = 0;
    for (int t = 1; t < LL; ++t) {
        asm volatile("bar.sync 1, 160;" ::: "memory");   // p, ring, k published

        int k = k_sm[buf];
        ktot += k;
        float scale = __int_as_float((unsigned)(127 - k) << 23);  // exact 2^-k

        float e   = ring[t & 7][i];
        float ee  = __expf(e);
        float ees = ee * scale;               // off chain
        float mkt = msk[t];
        float pprev = p_sm[buf][i];
        float wb_alt = pprev * scale;         // masked path, off chain

        const ulonglong2* pp2 = (const ulonglong2*)&p_sm[buf][j0];
        unsigned long long a0 = 0, a1 = 0, a2 = 0, a3 = 0;
        #pragma unroll
        for (int jj = 0; jj < 4; ++jj) {
            ulonglong2 v0 = pp2[2 * jj];
            ulonglong2 v1 = pp2[2 * jj + 1];
            a0 = fma2(E[4 * jj + 0], v0.x, a0);
            a1 = fma2(E[4 * jj + 1], v0.y, a1);
            a2 = fma2(E[4 * jj + 2], v1.x, a2);
            a3 = fma2(E[4 * jj + 3], v1.y, a3);
        }
        unsigned long long s01 = add2(a0, a1);
        unsigned long long s23 = add2(a2, a3);
        unsigned long long stot = add2(s01, s23);
        float slo, shi;
        asm("mov.b64 {%0, %1}, %2;" : "=f"(slo), "=f"(shi) : "l"(stot));
        float acc = slo + shi;
        acc += __shfl_xor_sync(0xffffffffu, acc, 1);

        float w = (mkt != 0.f) ? acc * ees : wb_alt;

        if (q == 0) p_sm[buf ^ 1][i] = w;
        if (tid == 0) {
            unsigned wbits = __float_as_uint(w);
            int kn = wbits ? (int)((wbits >> 23) & 255u) - 127 : 0;
            k_sm[buf ^ 1] = kn;
        }
        buf ^= 1;
    }

    asm volatile("bar.sync 1, 160;" ::: "memory");

    // final: out = lse_i( log(p_i) + K*ln2 + T[STOP,i] ), log2 space
    if (tid < 32) {
        float Kf = (float)ktot;
        float v0 = __log2f(p_sm[buf][tid])      + Kf + trans[STOP_TAG * C + tid]      * L2E;
        float v1 = __log2f(p_sm[buf][tid + 32]) + Kf + trans[STOP_TAG * C + tid + 32] * L2E;
        float mx = fmaxf(v0, v1);
        #pragma unroll
        for (int o = 16; o; o >>= 1) mx = fmaxf(mx, __shfl_xor_sync(0xffffffffu, mx, o));
        float sum = exp2f(v0 - mx) + exp2f(v1 - mx);
        #pragma unroll
        for (int o = 16; o; o >>= 1) sum += __shfl_xor_sync(0xffffffffu, sum, o);
        if (tid == 0) out[b] = (mx + __log2f(sum)) * LN2F;
    }
}

extern "C" void kernel_launch(void* const* d_in, const int* in_sizes, int n_in,
                              void* d_out, int out_size)
{
    const float* features = (const float*)d_in[0];
    const int*   ys32     = (const int*)d_in[1];
    const float* masks    = (const float*)d_in[2];
    const float* fc_w     = (const float*)d_in[3];
    const float* fc_b     = (const float*)d_in[4];
    const float* trans    = (const float*)d_in[5];
    float* out = (float*)d_out;

    cudaFuncSetAttribute(hmma_kernel, cudaFuncAttributeMaxDynamicSharedMemorySize,
                         SMEM_U32 * 4);

    wprep_kernel<<<128, 256>>>(fc_w);
    hmma_kernel<<<256, 256, SMEM_U32 * 4>>>(features, fc_b);
    forward_kernel<<<NB, 192>>>(masks, trans, ys32, out);
}

// round 17
// speedup vs baseline: 1.9174x; 1.1356x over previous
#include <cuda_runtime.h>
#include <cstdint>

#define C 66            // full tagset incl START/STOP (trans stride)
#define CT 64           // tracked tags (START/STOP provably inert)
#define START_TAG 64
#define STOP_TAG 65
#define NB 32
#define LL 1024
#define DD 1024
#define IMPOSSIBLE_F -10000.0f
#define L2E 1.4426950408889634f
#define LN2F 0.6931471805599453f

// scratch: emissions [B*L, 64] fp32 (8.4 MB)
__device__ float g_feats[(size_t)NB * LL * CT];
// W transposed + bf16 hi/lo split: [64 n][512 k-pairs] u32 (bf16x2)
__device__ unsigned g_wt_h[64 * 512];
__device__ unsigned g_wt_l[64 * 512];

#define CP_ASYNC16(dst_u32, src_ptr) \
    asm volatile("cp.async.ca.shared.global [%0], [%1], 16;\n" \
                 :: "r"(dst_u32), "l"(src_ptr))
#define CP_COMMIT() asm volatile("cp.async.commit_group;\n" ::: "memory")
#define CP_WAIT6()  asm volatile("cp.async.wait_group 6;\n" ::: "memory")

__device__ __forceinline__ void mma16816(float* d, const unsigned* a,
                                         unsigned b0, unsigned b1) {
    asm volatile(
        "mma.sync.aligned.m16n8k16.row.col.f32.bf16.bf16.f32 "
        "{%0,%1,%2,%3}, {%4,%5,%6,%7}, {%8,%9}, {%0,%1,%2,%3};\n"
        : "+f"(d[0]), "+f"(d[1]), "+f"(d[2]), "+f"(d[3])
        : "r"(a[0]), "r"(a[1]), "r"(a[2]), "r"(a[3]), "r"(b0), "r"(b1));
}

__device__ __forceinline__ unsigned long long fma2(unsigned long long a,
                                                   unsigned long long b,
                                                   unsigned long long c) {
    unsigned long long d;
    asm("fma.rn.f32x2 %0, %1, %2, %3;" : "=l"(d) : "l"(a), "l"(b), "l"(c));
    return d;
}
__device__ __forceinline__ unsigned long long add2(unsigned long long a,
                                                   unsigned long long b) {
    unsigned long long d;
    asm("add.rn.f32x2 %0, %1, %2;" : "=l"(d) : "l"(a), "l"(b));
    return d;
}
__device__ __forceinline__ unsigned long long pack2(float lo, float hi) {
    unsigned long long d;
    asm("mov.b64 %0, {%1, %2};" : "=l"(d) : "f"(lo), "f"(hi));
    return d;
}

// ---------------------------------------------------------------------------
// W prep: Wt[n][kp] = bf16x2{ W[2kp][n], W[2kp+1][n] } hi + residual lo.
// ---------------------------------------------------------------------------
__global__ void wprep_kernel(const float* __restrict__ W)
{
    int P = blockIdx.x * 256 + threadIdx.x;
    if (P >= 64 * 512) return;
    int n = P >> 9, kp = P & 511;
    float x0 = W[(size_t)(2 * kp) * C + n];
    float x1 = W[(size_t)(2 * kp + 1) * C + n];
    unsigned h;
    asm("cvt.rn.bf16x2.f32 %0, %1, %2;" : "=r"(h) : "f"(x1), "f"(x0));
    float l0 = x0 - __uint_as_float(h << 16);
    float l1 = x1 - __uint_as_float(h & 0xffff0000u);
    unsigned l;
    asm("cvt.rn.bf16x2.f32 %0, %1, %2;" : "=r"(l) : "f"(l1), "f"(l0));
    g_wt_h[P] = h;
    g_wt_l[P] = l;
}

// ---------------------------------------------------------------------------
// HMMA GEMM, 3-pass (validated R12/R13, rel_err 4.1e-6):
//   feats = Ah*Wh + Ah*Wl + Al*Wh + bias, f32 accum.
// CTA 256 thr / 8 warps, tile M=128 x N=64, 16 K-chunks of 64.
// ---------------------------------------------------------------------------
#define AH_OFF 0
#define AL_OFF 4608
#define BH_OFF 9216
#define BL_OFF 11520
#define BIAS_OFF 13824
#define SMEM_U32 13888

__global__ void __launch_bounds__(256, 2) hmma_kernel(
    const float* __restrict__ A, const float* __restrict__ bias)
{
    extern __shared__ unsigned sm[];
    unsigned* Ah = sm + AH_OFF;
    unsigned* Al = sm + AL_OFF;
    unsigned* Bh = sm + BH_OFF;
    unsigned* Bl = sm + BL_OFF;
    float* bsm = (float*)(sm + BIAS_OFF);

    const int tid = threadIdx.x;
    const int w = tid >> 5;
    const int lane = tid & 31;
    const int g = lane >> 2;
    const int tig = lane & 3;
    const int blockRow = blockIdx.x * 128;

    if (tid < 64) bsm[tid] = bias[tid];

    const int am = tid >> 1;
    const int ah = tid & 1;
    const float4* asrc = (const float4*)(A + (size_t)(blockRow + am) * DD + ah * 32);

    float4 pre[8];
    #pragma unroll
    for (int j = 0; j < 8; ++j) pre[j] = asrc[j];

    float acc[8][4];
    #pragma unroll
    for (int nt = 0; nt < 8; ++nt)
        #pragma unroll
        for (int r = 0; r < 4; ++r) acc[nt][r] = 0.f;

    const int m0 = w * 16;

    for (int chunk = 0; chunk < 16; ++chunk) {
        const unsigned abase = (unsigned)(am * 36 + ah * 16);
        #pragma unroll
        for (int j = 0; j < 8; ++j) {
            float4 v = pre[j];
            unsigned h0, h1, l0, l1;
            asm("cvt.rn.bf16x2.f32 %0, %1, %2;" : "=r"(h0) : "f"(v.y), "f"(v.x));
            asm("cvt.rn.bf16x2.f32 %0, %1, %2;" : "=r"(h1) : "f"(v.w), "f"(v.z));
            float r0 = v.x - __uint_as_float(h0 << 16);
            float r1 = v.y - __uint_as_float(h0 & 0xffff0000u);
            float r2 = v.z - __uint_as_float(h1 << 16);
            float r3 = v.w - __uint_as_float(h1 & 0xffff0000u);
            asm("cvt.rn.bf16x2.f32 %0, %1, %2;" : "=r"(l0) : "f"(r1), "f"(r0));
            asm("cvt.rn.bf16x2.f32 %0, %1, %2;" : "=r"(l1) : "f"(r3), "f"(r2));
            *(uint2*)&Ah[abase + 2 * j] = make_uint2(h0, h1);
            *(uint2*)&Al[abase + 2 * j] = make_uint2(l0, l1);
        }
        {
            const int n = tid >> 2;
            const int kb = (tid & 3) * 8;
            const uint4* gh = (const uint4*)(g_wt_h + n * 512 + chunk * 32 + kb);
            const uint4* gl = (const uint4*)(g_wt_l + n * 512 + chunk * 32 + kb);
            uint4 v0 = gh[0], v1 = gh[1];
            uint4 u0 = gl[0], u1 = gl[1];
            *(uint4*)&Bh[n * 36 + kb]     = v0;
            *(uint4*)&Bh[n * 36 + kb + 4] = v1;
            *(uint4*)&Bl[n * 36 + kb]     = u0;
            *(uint4*)&Bl[n * 36 + kb + 4] = u1;
        }
        __syncthreads();

        if (chunk + 1 < 16) {
            const float4* s2 = asrc + (chunk + 1) * 16;
            #pragma unroll
            for (int j = 0; j < 8; ++j) pre[j] = s2[j];
        }

        #pragma unroll
        for (int ks = 0; ks < 4; ++ks) {
            const unsigned kb = (unsigned)(ks * 8 + tig);
            unsigned ahi[4], alo[4];
            ahi[0] = Ah[(m0 + g) * 36 + kb];
            ahi[1] = Ah[(m0 + g + 8) * 36 + kb];
            ahi[2] = Ah[(m0 + g) * 36 + kb + 4];
            ahi[3] = Ah[(m0 + g + 8) * 36 + kb + 4];
            alo[0] = Al[(m0 + g) * 36 + kb];
            alo[1] = Al[(m0 + g + 8) * 36 + kb];
            alo[2] = Al[(m0 + g) * 36 + kb + 4];
            alo[3] = Al[(m0 + g + 8) * 36 + kb + 4];
            #pragma unroll
            for (int nt = 0; nt < 8; ++nt) {
                const unsigned bidx = (unsigned)((nt * 8 + g) * 36) + kb;
                unsigned bh0 = Bh[bidx], bh1 = Bh[bidx + 4];
                unsigned bl0 = Bl[bidx], bl1 = Bl[bidx + 4];
                mma16816(acc[nt], ahi, bh0, bh1);
                mma16816(acc[nt], ahi, bl0, bl1);
                mma16816(acc[nt], alo, bh0, bh1);
            }
        }
        __syncthreads();
    }

    const int r0 = blockRow + m0 + g;
    #pragma unroll
    for (int nt = 0; nt < 8; ++nt) {
        const int c = nt * 8 + tig * 2;
        float b0 = bsm[c], b1 = bsm[c + 1];
        float2 o0 = make_float2(acc[nt][0] + b0, acc[nt][1] + b1);
        float2 o1 = make_float2(acc[nt][2] + b0, acc[nt][3] + b1);
        *(float2*)&g_feats[(size_t)r0 * CT + c]       = o0;
        *(float2*)&g_feats[(size_t)(r0 + 8) * CT + c] = o1;
    }
}

// ---------------------------------------------------------------------------
// CRF forward, p-space, 128 threads:
//   warps 0-1 (tid 0-63):  recursion, 1 tag/lane, full 64-dot (32 FFMA2),
//                          no shfl (smem broadcast reads).
//   warp 2   (tid 64-95):  cp.async ring producer.
//   warp 3   (tid 96-127): gold score (no barrier).
// bar.sync 1,96 couples warps 0-2 once per step.
// ---------------------------------------------------------------------------
__global__ void __launch_bounds__(128, 1) forward_kernel(
    const float* __restrict__ masks, const float* __restrict__ trans,
    const int* __restrict__ ys32, float* __restrict__ out)
{
    const int b = blockIdx.x;
    const int tid = threadIdx.x;

    __shared__ __align__(16) float p_sm[2][CT];
    __shared__ int   k_sm[2];
    __shared__ float msk[LL];
    __shared__ __align__(16) float ring[8][CT];

    const float* fb = g_feats + (size_t)b * LL * CT;

    // ---------------- gold warp (warp 3) ----------------
    if (tid >= 96) {
        const int l = tid - 96;
        const int* wnd = ys32 + (size_t)b * LL;
        int v = 0;
        for (int idx = l; idx < 512; idx += 32) v |= wnd[2 * idx + 1];
        #pragma unroll
        for (int o = 16; o; o >>= 1) v |= __shfl_xor_sync(0xffffffffu, v, o);
        const int stride = (v == 0) ? 2 : 1;

        const int* yb = ys32 + (size_t)b * LL * stride;
        const float* mb = masks + (size_t)b * LL;
        float local = 0.f, mloc = 0.f;
        for (int t = l; t < LL; t += 32) {
            int y  = yb[t * stride];
            int yp = t ? yb[(t - 1) * stride] : START_TAG;
            y  = min(max(y,  0), CT - 1);
            yp = min(max(yp, 0), C - 1);
            float mk = mb[t];
            local += (trans[y * C + yp] + fb[(size_t)t * CT + y]) * mk;
            mloc  += mk;
        }
        #pragma unroll
        for (int o = 16; o; o >>= 1) {
            local += __shfl_xor_sync(0xffffffffu, local, o);
            mloc  += __shfl_xor_sync(0xffffffffu, mloc,  o);
        }
        if (l == 0) {
            int len = (int)(mloc + 0.5f);
            int last = (len > 0) ? yb[(len - 1) * stride] : START_TAG;
            last = min(max(last, 0), C - 1);
            out[NB + b] = local + trans[STOP_TAG * C + last];
        }
        return;
    }

    // ---------------- ring producer warp (warp 2) ----------------
    if (tid >= 64) {
        const int l = tid - 64;
        unsigned ring_u32 = (unsigned)__cvta_generic_to_shared(&ring[0][0]);
        if (l < 16) {
            #pragma unroll
            for (int s = 1; s <= 6; ++s) {
                CP_ASYNC16(ring_u32 + (unsigned)((s & 7) * 256 + l * 16),
                           fb + (size_t)s * CT + l * 4);
                CP_COMMIT();
            }
        }
        for (int t = 1; t < LL; ++t) {
            if (l < 16) {
                int tp6 = t + 6;
                if (tp6 < LL)
                    CP_ASYNC16(ring_u32 + (unsigned)((tp6 & 7) * 256 + l * 16),
                               fb + (size_t)tp6 * CT + l * 4);
                CP_COMMIT();
                CP_WAIT6();
            }
            asm volatile("bar.sync 1, 96;" ::: "memory");
        }
        asm volatile("bar.sync 1, 96;" ::: "memory");   // final
        return;
    }

    // ---------------- recursion warps (0-1), tag i = tid ----------------
    const int i = tid;

    unsigned long long E[32];     // full exp(T) row, packed f32x2
    #pragma unroll
    for (int jj = 0; jj < 32; ++jj) {
        float e0 = expf(trans[i * C + 2 * jj]);
        float e1 = expf(trans[i * C + 2 * jj + 1]);
        E[jj] = pack2(e0, e1);
    }

    const float* mb = masks + (size_t)b * LL;
    for (int idx = tid; idx < LL; idx += 64) msk[idx] = mb[idx];

    {
        float mk0 = mb[0];
        float s0 = (mk0 != 0.f) ? (trans[i * C + START_TAG] + fb[i]) : IMPOSSIBLE_F;
        p_sm[0][i] = expf(s0);
    }
    if (tid == 0) { k_sm[0] = 0; k_sm[1] = 0; }

    int ktot = 0;
    int buf = 0;
    for (int t = 1; t < LL; ++t) {
        asm volatile("bar.sync 1, 96;" ::: "memory");   // p, ring, k published

        int k = k_sm[buf];
        ktot += k;
        float scale = __int_as_float((unsigned)(127 - k) << 23);  // exact 2^-k

        float e   = ring[t & 7][i];
        float ee  = __expf(e);
        float ees = ee * scale;               // off chain
        float mkt = msk[t];
        float pprev = p_sm[buf][i];
        float wb_alt = pprev * scale;         // masked path, off chain

        const ulonglong2* pp2 = (const ulonglong2*)&p_sm[buf][0];
        unsigned long long a0 = 0, a1 = 0, a2 = 0, a3 = 0;
        #pragma unroll
        for (int jj = 0; jj < 16; jj += 2) {
            ulonglong2 v0 = pp2[jj];
            ulonglong2 v1 = pp2[jj + 1];
            a0 = fma2(E[2 * jj + 0], v0.x, a0);
            a1 = fma2(E[2 * jj + 1], v0.y, a1);
            a2 = fma2(E[2 * jj + 2], v1.x, a2);
            a3 = fma2(E[2 * jj + 3], v1.y, a3);
        }
        unsigned long long s01 = add2(a0, a1);
        unsigned long long s23 = add2(a2, a3);
        unsigned long long stot = add2(s01, s23);
        float slo, shi;
        asm("mov.b64 {%0, %1}, %2;" : "=f"(slo), "=f"(shi) : "l"(stot));
        float acc = slo + shi;

        float w = (mkt != 0.f) ? acc * ees : wb_alt;

        p_sm[buf ^ 1][i] = w;
        if (tid == 0) {
            unsigned wbits = __float_as_uint(w);
            int kn = wbits ? (int)((wbits >> 23) & 255u) - 127 : 0;
            k_sm[buf ^ 1] = kn;
        }
        buf ^= 1;
    }

    asm volatile("bar.sync 1, 96;" ::: "memory");

    // final: out = lse_i( log(p_i) + K*ln2 + T[STOP,i] ), log2 space
    if (tid < 32) {
        float Kf = (float)ktot;
        float v0 = __log2f(p_sm[buf][tid])      + Kf + trans[STOP_TAG * C + tid]      * L2E;
        float v1 = __log2f(p_sm[buf][tid + 32]) + Kf + trans[STOP_TAG * C + tid + 32] * L2E;
        float mx = fmaxf(v0, v1);
        #pragma unroll
        for (int o = 16; o; o >>= 1) mx = fmaxf(mx, __shfl_xor_sync(0xffffffffu, mx, o));
        float sum = exp2f(v0 - mx) + exp2f(v1 - mx);
        #pragma unroll
        for (int o = 16; o; o >>= 1) sum += __shfl_xor_sync(0xffffffffu, sum, o);
        if (tid == 0) out[b] = (mx + __log2f(sum)) * LN2F;
    }
}

extern "C" void kernel_launch(void* const* d_in, const int* in_sizes, int n_in,
                              void* d_out, int out_size)
{
    const float* features = (const float*)d_in[0];
    const int*   ys32     = (const int*)d_in[1];
    const float* masks    = (const float*)d_in[2];
    const float* fc_w     = (const float*)d_in[3];
    const float* fc_b     = (const float*)d_in[4];
    const float* trans    = (const float*)d_in[5];
    float* out = (float*)d_out;

    cudaFuncSetAttribute(hmma_kernel, cudaFuncAttributeMaxDynamicSharedMemorySize,
                         SMEM_U32 * 4);

    wprep_kernel<<<128, 256>>>(fc_w);
    hmma_kernel<<<256, 256, SMEM_U32 * 4>>>(features, fc_b);
    forward_kernel<<<NB, 128>>>(masks, trans, ys32, out);
}